// round 12
// baseline (speedup 1.0000x reference)
#include <cuda_runtime.h>

#define NRAYS    16384
#define NSAMPLES 1024
#define EPS      0.05f
#define THREADS  256          // 256 threads x 4 samples = 1024 samples = 1 ray
#define NSLOTS   32

// ---------------- scratch (no allocation allowed) ----------------
__device__ double       g_slot_e[NSLOTS];
__device__ double       g_slot_n[NSLOTS];
__device__ double       g_slot_m[NSLOTS];
__device__ int          g_mask_kind;   // 0 = u8/bool, 1 = int32, 2 = float32
__device__ unsigned int g_done;        // block-completion ticket

// ---------------- init: zero accumulators + detect mask dtype ----------------
// Scans the first NRAYS bytes of the mask buffer (in-bounds for u8, i32 and
// f32 layouts) with uint4 loads. Classifies by which byte offsets (mod 4)
// ever hold nonzero:
//   u8 bool  : nonzeros at offset 1 (and others)
//   int32 0/1: nonzeros only at offset 0
//   f32 0/1  : 1.0f = 00 00 80 3F -> nonzeros at offsets 2/3 only
__global__ void init_detect_kernel(const uint4* __restrict__ mask_vec) {
    __shared__ int s_flags[8];
    const int tid  = threadIdx.x;
    const int warp = tid >> 5;

    int local = 0;
    #pragma unroll
    for (int k = 0; k < 4; k++) {
        const uint4 v = mask_vec[k * 256 + tid];
        const unsigned int w0 = v.x | v.y | v.z | v.w;  // OR keeps byte lanes
        if (w0 & 0x000000FFu) local |= 0x1;             // offset 0
        if (w0 & 0x0000FF00u) local |= 0x2;             // offset 1
        if (w0 & 0xFFFF0000u) local |= 0xC;             // offsets 2/3
    }
    local = __reduce_or_sync(0xFFFFFFFFu, local);
    if ((tid & 31) == 0) s_flags[warp] = local;

    // zero the reduction slots + ticket in parallel
    if (tid < NSLOTS) {
        g_slot_e[tid] = 0.0;
        g_slot_n[tid] = 0.0;
        g_slot_m[tid] = 0.0;
    }
    __syncthreads();

    if (tid == 0) {
        int f = 0;
        #pragma unroll
        for (int i = 0; i < 8; i++) f |= s_flags[i];
        int kind;
        if      (f & 0x2) kind = 0;   // byte offset 1 nonzero -> bool/u8
        else if (f & 0xC) kind = 2;   // offsets 2/3 -> float32
        else if (f & 0x1) kind = 1;   // only offset 0 -> int32
        else              kind = 0;   // degenerate (all-false mask)
        g_mask_kind = kind;
        g_done      = 0u;
    }
}

// ---------------- mask fetch per detected dtype ----------------
__device__ __forceinline__ float fetch_mask(const void* mask, int ray, int kind) {
    if (kind == 0)      return ((const unsigned char*)mask)[ray] ? 1.0f : 0.0f;
    else if (kind == 1) return ((const int*)mask)[ray]           ? 1.0f : 0.0f;
    else                return (((const float*)mask)[ray] != 0.0f) ? 1.0f : 0.0f;
}

// ---------------- main: one block per ray, single pass, w-load skipping ----
__global__ __launch_bounds__(THREADS) void loss_kernel(
    const float* __restrict__ ray_depth,
    const float* __restrict__ z_vals,
    const float* __restrict__ weights,
    const void*  __restrict__ mask,
    float*       __restrict__ out)
{
    const int ray  = blockIdx.x;
    const int t    = threadIdx.x;
    const int lane = t & 31;
    const int warp = t >> 5;

    // thread 0 fetches the ray mask early (latency overlaps the z/w stream)
    float m = 0.0f;
    if (t == 0) m = fetch_mask(mask, ray, g_mask_kind);

    const float d  = __ldg(&ray_depth[ray]);     // same addr per block -> broadcast
    const float lo = d - EPS;
    const float hi = d + EPS;

    // thread t owns samples [4t, 4t+4): one float4 of z, conditionally one of w
    const float4 z = __ldcs((const float4*)z_vals + (size_t)ray * (NSAMPLES / 4) + t);

    float e = 0.0f;   // sum w^2 where z <  lo
    float n = 0.0f;   // sum w   where lo <= z < hi

    // z sorted within the chunk: if the chunk minimum z.x >= hi, the whole
    // chunk contributes nothing -> skip the weights load entirely.
    if (z.x < hi) {
        const float4 w = __ldcs((const float4*)weights + (size_t)ray * (NSAMPLES / 4) + t);
        if (z.x < lo) e = fmaf(w.x, w.x, e); else               n += w.x;  // z.x < hi known
        if (z.y < lo) e = fmaf(w.y, w.y, e); else if (z.y < hi) n += w.y;
        if (z.z < lo) e = fmaf(w.z, w.z, e); else if (z.z < hi) n += w.z;
        if (z.w < lo) e = fmaf(w.w, w.w, e); else if (z.w < hi) n += w.w;
    }

    // warp tree-reduce
    #pragma unroll
    for (int off = 16; off > 0; off >>= 1) {
        e += __shfl_xor_sync(0xFFFFFFFFu, e, off);
        n += __shfl_xor_sync(0xFFFFFFFFu, n, off);
    }

    __shared__ float s_e[8], s_n[8];
    if (lane == 0) { s_e[warp] = e; s_n[warp] = n; }
    __syncthreads();

    if (t == 0) {
        float E = 0.0f, N = 0.0f;
        #pragma unroll
        for (int i = 0; i < 8; i++) { E += s_e[i]; N += s_n[i]; }
        const float dn   = 1.0f - N;
        const int   slot = ray & (NSLOTS - 1);
        atomicAdd(&g_slot_e[slot], (double)(E * m));
        atomicAdd(&g_slot_n[slot], (double)(dn * dn * m));
        atomicAdd(&g_slot_m[slot], (double)m);

        // last block folds the slots and finalizes (no extra kernel)
        __threadfence();
        const unsigned int ticket = atomicAdd(&g_done, 1u);
        if (ticket == (unsigned int)(NRAYS - 1)) {
            double se = 0.0, sn = 0.0, sm = 0.0;
            #pragma unroll
            for (int i = 0; i < NSLOTS; i++) {
                se += g_slot_e[i]; sn += g_slot_n[i]; sm += g_slot_m[i];
            }
            out[0] = (float)(se / sm);   // loss_empty
            out[1] = (float)(sn / sm);   // loss_near
        }
    }
}

// ---------------- launch ----------------
extern "C" void kernel_launch(void* const* d_in, const int* in_sizes, int n_in,
                              void* d_out, int out_size) {
    const float* ray_depth = (const float*)d_in[0];   // [16384, 1]
    const float* z_vals    = (const float*)d_in[1];   // [16384, 1024] sorted
    const float* weights   = (const float*)d_in[2];   // [16384, 1024]
    const void*  ray_mask  = d_in[3];                 // [16384] bool/i32/f32

    init_detect_kernel<<<1, 256>>>((const uint4*)ray_mask);
    loss_kernel<<<NRAYS, THREADS>>>(ray_depth, z_vals, weights, ray_mask, (float*)d_out);
}

// round 13
// speedup vs baseline: 1.0008x; 1.0008x over previous
#include <cuda_runtime.h>

#define NRAYS    16384
#define NSAMPLES 1024
#define EPS      0.05f
#define THREADS  256          // 256 threads x 4 samples = 1024 samples = 1 ray
#define NSLOTS   32

// ---------------- scratch (no allocation allowed) ----------------
__device__ double       g_slot_e[NSLOTS];
__device__ double       g_slot_n[NSLOTS];
__device__ double       g_slot_m[NSLOTS];
__device__ int          g_mask_kind;   // 0 = u8/bool, 1 = int32, 2 = float32
__device__ unsigned int g_done;        // block-completion ticket

// ---------------- init: zero accumulators + detect mask dtype ----------------
// Scans the first NRAYS bytes of the mask buffer (in-bounds for u8, i32 and
// f32 layouts) with uint4 loads. Classifies by which byte offsets (mod 4)
// ever hold nonzero:
//   u8 bool  : nonzeros at offset 1 (and others)
//   int32 0/1: nonzeros only at offset 0
//   f32 0/1  : 1.0f = 00 00 80 3F -> nonzeros at offsets 2/3 only
__global__ void init_detect_kernel(const uint4* __restrict__ mask_vec) {
    __shared__ int s_flags[8];
    const int tid  = threadIdx.x;
    const int warp = tid >> 5;

    int local = 0;
    #pragma unroll
    for (int k = 0; k < 4; k++) {
        const uint4 v = mask_vec[k * 256 + tid];
        const unsigned int w0 = v.x | v.y | v.z | v.w;  // OR keeps byte lanes
        if (w0 & 0x000000FFu) local |= 0x1;             // offset 0
        if (w0 & 0x0000FF00u) local |= 0x2;             // offset 1
        if (w0 & 0xFFFF0000u) local |= 0xC;             // offsets 2/3
    }
    local = __reduce_or_sync(0xFFFFFFFFu, local);
    if ((tid & 31) == 0) s_flags[warp] = local;

    // zero the reduction slots + ticket in parallel
    if (tid < NSLOTS) {
        g_slot_e[tid] = 0.0;
        g_slot_n[tid] = 0.0;
        g_slot_m[tid] = 0.0;
    }
    __syncthreads();

    if (tid == 0) {
        int f = 0;
        #pragma unroll
        for (int i = 0; i < 8; i++) f |= s_flags[i];
        int kind;
        if      (f & 0x2) kind = 0;   // byte offset 1 nonzero -> bool/u8
        else if (f & 0xC) kind = 2;   // offsets 2/3 -> float32
        else if (f & 0x1) kind = 1;   // only offset 0 -> int32
        else              kind = 0;   // degenerate (all-false mask)
        g_mask_kind = kind;
        g_done      = 0u;
    }
}

// ---------------- mask fetch per detected dtype ----------------
__device__ __forceinline__ float fetch_mask(const void* mask, int ray, int kind) {
    if (kind == 0)      return ((const unsigned char*)mask)[ray] ? 1.0f : 0.0f;
    else if (kind == 1) return ((const int*)mask)[ray]           ? 1.0f : 0.0f;
    else                return (((const float*)mask)[ray] != 0.0f) ? 1.0f : 0.0f;
}

// ---------------- main: one block per ray, single pass, w-load skipping ----
__global__ __launch_bounds__(THREADS) void loss_kernel(
    const float* __restrict__ ray_depth,
    const float* __restrict__ z_vals,
    const float* __restrict__ weights,
    const void*  __restrict__ mask,
    float*       __restrict__ out)
{
    const int ray  = blockIdx.x;
    const int t    = threadIdx.x;
    const int lane = t & 31;
    const int warp = t >> 5;

    // thread 0 fetches the ray mask early (latency overlaps the z/w stream)
    float m = 0.0f;
    if (t == 0) m = fetch_mask(mask, ray, g_mask_kind);

    const float d  = __ldg(&ray_depth[ray]);     // same addr per block -> broadcast
    const float lo = d - EPS;
    const float hi = d + EPS;

    // thread t owns samples [4t, 4t+4): one float4 of z, conditionally one of w
    const float4 z = __ldcs((const float4*)z_vals + (size_t)ray * (NSAMPLES / 4) + t);

    float e = 0.0f;   // sum w^2 where z <  lo
    float n = 0.0f;   // sum w   where lo <= z < hi

    // z sorted within the chunk: if the chunk minimum z.x >= hi, the whole
    // chunk contributes nothing -> skip the weights load entirely.
    if (z.x < hi) {
        const float4 w = __ldcs((const float4*)weights + (size_t)ray * (NSAMPLES / 4) + t);
        if (z.x < lo) e = fmaf(w.x, w.x, e); else               n += w.x;  // z.x < hi known
        if (z.y < lo) e = fmaf(w.y, w.y, e); else if (z.y < hi) n += w.y;
        if (z.z < lo) e = fmaf(w.z, w.z, e); else if (z.z < hi) n += w.z;
        if (z.w < lo) e = fmaf(w.w, w.w, e); else if (z.w < hi) n += w.w;
    }

    // warp tree-reduce
    #pragma unroll
    for (int off = 16; off > 0; off >>= 1) {
        e += __shfl_xor_sync(0xFFFFFFFFu, e, off);
        n += __shfl_xor_sync(0xFFFFFFFFu, n, off);
    }

    __shared__ float s_e[8], s_n[8];
    if (lane == 0) { s_e[warp] = e; s_n[warp] = n; }
    __syncthreads();

    if (t == 0) {
        float E = 0.0f, N = 0.0f;
        #pragma unroll
        for (int i = 0; i < 8; i++) { E += s_e[i]; N += s_n[i]; }
        const float dn   = 1.0f - N;
        const int   slot = ray & (NSLOTS - 1);
        atomicAdd(&g_slot_e[slot], (double)(E * m));
        atomicAdd(&g_slot_n[slot], (double)(dn * dn * m));
        atomicAdd(&g_slot_m[slot], (double)m);

        // last block folds the slots and finalizes (no extra kernel)
        __threadfence();
        const unsigned int ticket = atomicAdd(&g_done, 1u);
        if (ticket == (unsigned int)(NRAYS - 1)) {
            double se = 0.0, sn = 0.0, sm = 0.0;
            #pragma unroll
            for (int i = 0; i < NSLOTS; i++) {
                se += g_slot_e[i]; sn += g_slot_n[i]; sm += g_slot_m[i];
            }
            out[0] = (float)(se / sm);   // loss_empty
            out[1] = (float)(sn / sm);   // loss_near
        }
    }
}

// ---------------- launch ----------------
extern "C" void kernel_launch(void* const* d_in, const int* in_sizes, int n_in,
                              void* d_out, int out_size) {
    const float* ray_depth = (const float*)d_in[0];   // [16384, 1]
    const float* z_vals    = (const float*)d_in[1];   // [16384, 1024] sorted
    const float* weights   = (const float*)d_in[2];   // [16384, 1024]
    const void*  ray_mask  = d_in[3];                 // [16384] bool/i32/f32

    init_detect_kernel<<<1, 256>>>((const uint4*)ray_mask);
    loss_kernel<<<NRAYS, THREADS>>>(ray_depth, z_vals, weights, ray_mask, (float*)d_out);
}

// round 16
// speedup vs baseline: 1.0031x; 1.0023x over previous
#include <cuda_runtime.h>

#define NRAYS    16384
#define NSAMPLES 1024
#define EPS      0.05f
#define THREADS  256          // 256 threads x 4 samples = 1024 samples = 1 ray
#define NSLOTS   32

// ---------------- scratch (no allocation allowed) ----------------
__device__ double       g_slot_e[NSLOTS];
__device__ double       g_slot_n[NSLOTS];
__device__ double       g_slot_m[NSLOTS];
__device__ int          g_mask_kind;   // 0 = u8/bool, 1 = int32, 2 = float32
__device__ unsigned int g_done;        // block-completion ticket

// ---------------- init: zero accumulators + detect mask dtype ----------------
// Scans the first NRAYS bytes of the mask buffer (in-bounds for u8, i32 and
// f32 layouts) with uint4 loads. Classifies by which byte offsets (mod 4)
// ever hold nonzero:
//   u8 bool  : nonzeros at offset 1 (and others)
//   int32 0/1: nonzeros only at offset 0
//   f32 0/1  : 1.0f = 00 00 80 3F -> nonzeros at offsets 2/3 only
__global__ void init_detect_kernel(const uint4* __restrict__ mask_vec) {
    __shared__ int s_flags[8];
    const int tid  = threadIdx.x;
    const int warp = tid >> 5;

    int local = 0;
    #pragma unroll
    for (int k = 0; k < 4; k++) {
        const uint4 v = mask_vec[k * 256 + tid];
        const unsigned int w0 = v.x | v.y | v.z | v.w;  // OR keeps byte lanes
        if (w0 & 0x000000FFu) local |= 0x1;             // offset 0
        if (w0 & 0x0000FF00u) local |= 0x2;             // offset 1
        if (w0 & 0xFFFF0000u) local |= 0xC;             // offsets 2/3
    }
    local = __reduce_or_sync(0xFFFFFFFFu, local);
    if ((tid & 31) == 0) s_flags[warp] = local;

    // zero the reduction slots + ticket in parallel
    if (tid < NSLOTS) {
        g_slot_e[tid] = 0.0;
        g_slot_n[tid] = 0.0;
        g_slot_m[tid] = 0.0;
    }
    __syncthreads();

    if (tid == 0) {
        int f = 0;
        #pragma unroll
        for (int i = 0; i < 8; i++) f |= s_flags[i];
        int kind;
        if      (f & 0x2) kind = 0;   // byte offset 1 nonzero -> bool/u8
        else if (f & 0xC) kind = 2;   // offsets 2/3 -> float32
        else if (f & 0x1) kind = 1;   // only offset 0 -> int32
        else              kind = 0;   // degenerate (all-false mask)
        g_mask_kind = kind;
        g_done      = 0u;
    }
}

// ---------------- mask fetch per detected dtype ----------------
__device__ __forceinline__ float fetch_mask(const void* mask, int ray, int kind) {
    if (kind == 0)      return ((const unsigned char*)mask)[ray] ? 1.0f : 0.0f;
    else if (kind == 1) return ((const int*)mask)[ray]           ? 1.0f : 0.0f;
    else                return (((const float*)mask)[ray] != 0.0f) ? 1.0f : 0.0f;
}

// ---------------- main: one block per ray, single pass, w-load skipping ----
__global__ __launch_bounds__(THREADS) void loss_kernel(
    const float* __restrict__ ray_depth,
    const float* __restrict__ z_vals,
    const float* __restrict__ weights,
    const void*  __restrict__ mask,
    float*       __restrict__ out)
{
    const int ray  = blockIdx.x;
    const int t    = threadIdx.x;
    const int lane = t & 31;
    const int warp = t >> 5;

    // thread 0 fetches the ray mask early (latency overlaps the z/w stream)
    float m = 0.0f;
    if (t == 0) m = fetch_mask(mask, ray, g_mask_kind);

    const float d  = __ldg(&ray_depth[ray]);     // same addr per block -> broadcast
    const float lo = d - EPS;
    const float hi = d + EPS;

    // thread t owns samples [4t, 4t+4): one float4 of z, conditionally one of w
    const float4 z = __ldcs((const float4*)z_vals + (size_t)ray * (NSAMPLES / 4) + t);

    float e = 0.0f;   // sum w^2 where z <  lo
    float n = 0.0f;   // sum w   where lo <= z < hi

    // z sorted within the chunk: if the chunk minimum z.x >= hi, the whole
    // chunk contributes nothing -> skip the weights load entirely.
    if (z.x < hi) {
        const float4 w = __ldcs((const float4*)weights + (size_t)ray * (NSAMPLES / 4) + t);
        if (z.x < lo) e = fmaf(w.x, w.x, e); else               n += w.x;  // z.x < hi known
        if (z.y < lo) e = fmaf(w.y, w.y, e); else if (z.y < hi) n += w.y;
        if (z.z < lo) e = fmaf(w.z, w.z, e); else if (z.z < hi) n += w.z;
        if (z.w < lo) e = fmaf(w.w, w.w, e); else if (z.w < hi) n += w.w;
    }

    // warp tree-reduce
    #pragma unroll
    for (int off = 16; off > 0; off >>= 1) {
        e += __shfl_xor_sync(0xFFFFFFFFu, e, off);
        n += __shfl_xor_sync(0xFFFFFFFFu, n, off);
    }

    __shared__ float s_e[8], s_n[8];
    if (lane == 0) { s_e[warp] = e; s_n[warp] = n; }
    __syncthreads();

    if (t == 0) {
        float E = 0.0f, N = 0.0f;
        #pragma unroll
        for (int i = 0; i < 8; i++) { E += s_e[i]; N += s_n[i]; }
        const float dn   = 1.0f - N;
        const int   slot = ray & (NSLOTS - 1);
        atomicAdd(&g_slot_e[slot], (double)(E * m));
        atomicAdd(&g_slot_n[slot], (double)(dn * dn * m));
        atomicAdd(&g_slot_m[slot], (double)m);

        // last block folds the slots and finalizes (no extra kernel)
        __threadfence();
        const unsigned int ticket = atomicAdd(&g_done, 1u);
        if (ticket == (unsigned int)(NRAYS - 1)) {
            double se = 0.0, sn = 0.0, sm = 0.0;
            #pragma unroll
            for (int i = 0; i < NSLOTS; i++) {
                se += g_slot_e[i]; sn += g_slot_n[i]; sm += g_slot_m[i];
            }
            out[0] = (float)(se / sm);   // loss_empty
            out[1] = (float)(sn / sm);   // loss_near
        }
    }
}

// ---------------- launch ----------------
extern "C" void kernel_launch(void* const* d_in, const int* in_sizes, int n_in,
                              void* d_out, int out_size) {
    const float* ray_depth = (const float*)d_in[0];   // [16384, 1]
    const float* z_vals    = (const float*)d_in[1];   // [16384, 1024] sorted
    const float* weights   = (const float*)d_in[2];   // [16384, 1024]
    const void*  ray_mask  = d_in[3];                 // [16384] bool/i32/f32

    init_detect_kernel<<<1, 256>>>((const uint4*)ray_mask);
    loss_kernel<<<NRAYS, THREADS>>>(ray_depth, z_vals, weights, ray_mask, (float*)d_out);
}

// round 17
// speedup vs baseline: 1.1122x; 1.1087x over previous
#include <cuda_runtime.h>

#define NRAYS    16384
#define NSAMPLES 1024
#define EPS      0.05f
#define THREADS  64            // 2 warps per block, warp-per-ray, no block reduce
#define WARPS_PB (THREADS / 32)
#define GRID     (NRAYS / WARPS_PB)   // 8192 blocks
#define NSLOTS   32

// ---------------- scratch (no allocation allowed) ----------------
__device__ double       g_slot_e[NSLOTS];
__device__ double       g_slot_n[NSLOTS];
__device__ double       g_slot_m[NSLOTS];
__device__ int          g_mask_kind;   // 0 = u8/bool, 1 = int32, 2 = float32
__device__ unsigned int g_done;        // warp-completion ticket

// ---------------- init: zero accumulators + detect mask dtype ----------------
// Scans the first NRAYS bytes of the mask buffer (in-bounds for u8, i32 and
// f32 layouts) with uint4 loads. Classifies by which byte offsets (mod 4)
// ever hold nonzero:
//   u8 bool  : nonzeros at offset 1 (and others)
//   int32 0/1: nonzeros only at offset 0
//   f32 0/1  : 1.0f = 00 00 80 3F -> nonzeros at offsets 2/3 only
__global__ void init_detect_kernel(const uint4* __restrict__ mask_vec) {
    __shared__ int s_flags[8];
    const int tid  = threadIdx.x;
    const int warp = tid >> 5;

    int local = 0;
    #pragma unroll
    for (int k = 0; k < 4; k++) {
        const uint4 v = mask_vec[k * 256 + tid];
        const unsigned int w0 = v.x | v.y | v.z | v.w;  // OR keeps byte lanes
        if (w0 & 0x000000FFu) local |= 0x1;             // offset 0
        if (w0 & 0x0000FF00u) local |= 0x2;             // offset 1
        if (w0 & 0xFFFF0000u) local |= 0xC;             // offsets 2/3
    }
    local = __reduce_or_sync(0xFFFFFFFFu, local);
    if ((tid & 31) == 0) s_flags[warp] = local;

    if (tid < NSLOTS) {
        g_slot_e[tid] = 0.0;
        g_slot_n[tid] = 0.0;
        g_slot_m[tid] = 0.0;
    }
    __syncthreads();

    if (tid == 0) {
        int f = 0;
        #pragma unroll
        for (int i = 0; i < 8; i++) f |= s_flags[i];
        int kind;
        if      (f & 0x2) kind = 0;   // byte offset 1 nonzero -> bool/u8
        else if (f & 0xC) kind = 2;   // offsets 2/3 -> float32
        else if (f & 0x1) kind = 1;   // only offset 0 -> int32
        else              kind = 0;   // degenerate (all-false mask)
        g_mask_kind = kind;
        g_done      = 0u;
    }
}

// ---------------- mask fetch per detected dtype ----------------
__device__ __forceinline__ float fetch_mask(const void* mask, int ray, int kind) {
    if (kind == 0)      return ((const unsigned char*)mask)[ray] ? 1.0f : 0.0f;
    else if (kind == 1) return ((const int*)mask)[ray]           ? 1.0f : 0.0f;
    else                return (((const float*)mask)[ray] != 0.0f) ? 1.0f : 0.0f;
}

// ---------------- main: warp per ray, sorted early-exit stream --------------
__global__ __launch_bounds__(THREADS) void loss_kernel(
    const float* __restrict__ ray_depth,
    const float* __restrict__ z_vals,
    const float* __restrict__ weights,
    const void*  __restrict__ mask,
    float*       __restrict__ out)
{
    const int lane = threadIdx.x & 31;
    const int ray  = blockIdx.x * WARPS_PB + (threadIdx.x >> 5);  // exact

    // lane 0 fetches the ray mask early; latency overlaps the stream
    float m = 0.0f;
    if (lane == 0) m = fetch_mask(mask, ray, g_mask_kind);

    const float d  = __ldg(&ray_depth[ray]);     // broadcast (same addr per warp)
    const float lo = d - EPS;
    const float hi = d + EPS;

    const float4* __restrict__ zp = (const float4*)z_vals  + (size_t)ray * (NSAMPLES / 4);
    const float4* __restrict__ wp = (const float4*)weights + (size_t)ray * (NSAMPLES / 4);

    float e = 0.0f;   // sum w^2 where z <  lo
    float n = 0.0f;   // sum w   where lo <= z < hi

    // iteration k covers samples [128k, 128k+128); min z is lane 0's z.x.
    // Once that min >= hi, this and every later iteration contribute nothing.
    float4 z = __ldcs(&zp[lane]);                // prefetch k=0
    #pragma unroll
    for (int k = 0; k < NSAMPLES / 128; k++) {   // up to 8 iterations
        const float zmin = __shfl_sync(0xFFFFFFFFu, z.x, 0);
        if (zmin >= hi) break;                   // warp-uniform exit

        const float4 w = __ldcs(&wp[k * 32 + lane]);
        float4 znext;
        if (k < NSAMPLES / 128 - 1) znext = __ldcs(&zp[(k + 1) * 32 + lane]);

        if (z.x < lo) e = fmaf(w.x, w.x, e); else if (z.x < hi) n += w.x;
        if (z.y < lo) e = fmaf(w.y, w.y, e); else if (z.y < hi) n += w.y;
        if (z.z < lo) e = fmaf(w.z, w.z, e); else if (z.z < hi) n += w.z;
        if (z.w < lo) e = fmaf(w.w, w.w, e); else if (z.w < hi) n += w.w;

        z = znext;
    }

    // warp tree-reduce both sums
    #pragma unroll
    for (int off = 16; off > 0; off >>= 1) {
        e += __shfl_xor_sync(0xFFFFFFFFu, e, off);
        n += __shfl_xor_sync(0xFFFFFFFFu, n, off);
    }

    // lane 0 accumulates directly into spread slots (no block reduce needed)
    if (lane == 0) {
        const float dn   = 1.0f - n;
        const int   slot = ray & (NSLOTS - 1);
        atomicAdd(&g_slot_e[slot], (double)(e * m));
        atomicAdd(&g_slot_n[slot], (double)(dn * dn * m));
        atomicAdd(&g_slot_m[slot], (double)m);

        // last warp folds the slots and finalizes (no extra kernel)
        __threadfence();
        const unsigned int ticket = atomicAdd(&g_done, 1u);
        if (ticket == (unsigned int)(NRAYS - 1)) {
            double se = 0.0, sn = 0.0, sm = 0.0;
            #pragma unroll
            for (int i = 0; i < NSLOTS; i++) {
                se += g_slot_e[i]; sn += g_slot_n[i]; sm += g_slot_m[i];
            }
            out[0] = (float)(se / sm);   // loss_empty
            out[1] = (float)(sn / sm);   // loss_near
        }
    }
}

// ---------------- launch ----------------
extern "C" void kernel_launch(void* const* d_in, const int* in_sizes, int n_in,
                              void* d_out, int out_size) {
    const float* ray_depth = (const float*)d_in[0];   // [16384, 1]
    const float* z_vals    = (const float*)d_in[1];   // [16384, 1024] sorted
    const float* weights   = (const float*)d_in[2];   // [16384, 1024]
    const void*  ray_mask  = d_in[3];                 // [16384] bool/i32/f32

    init_detect_kernel<<<1, 256>>>((const uint4*)ray_mask);
    loss_kernel<<<GRID, THREADS>>>(ray_depth, z_vals, weights, ray_mask, (float*)d_out);
}